// round 4
// baseline (speedup 1.0000x reference)
#include <cuda_runtime.h>
#include <math.h>

#define B_    16
#define C_    128
#define HIM   32
#define WIM   32
#define NTOK  640
#define S_    256     // spatial 16x16 == GEMM K == EMB
#define EMBD  256
#define NHEAD 8
#define DH    32
#define BH    128     // B_*NHEAD
#define T_    640
#define NH    8       // n_hashes
#define NB    10      // n_buckets per hash
#define NC    80      // chunks per bh (NH*NB)

// ---------------- scratch (device globals; no allocation allowed) ----------
__device__ float g_tokens[B_ * NTOK * S_];        // (b, n, s)
__device__ float g_qk[BH * T_ * DH];              // (bh, t, d)
__device__ float g_v [BH * T_ * DH];
__device__ int   g_bkt[BH * NH * T_];             // bucket in [0,10)
__device__ int   g_st [BH * NH * T_];             // sorted pos -> token id
__device__ float g_oh [BH * NH * T_ * DH];        // per-hash output (scattered by token)
__device__ float g_lse[BH * NH * T_];
__device__ float g_of [BH * T_ * DH];             // combined over hashes

// ---------------- stage 1: maxpool + Haar -> tokens ------------------------
__global__ __launch_bounds__(256) void k_tokens(const float* __restrict__ x) {
    int idx = blockIdx.x * 256 + threadIdx.x;
    if (idx >= B_ * NTOK * S_) return;
    int s = idx & 255;
    int n = (idx >> 8) % NTOK;
    int b = idx / (NTOK * S_);
    int hh = s >> 4, ww = s & 15;
    float val;
    if (n < 128) {
        const float* xp = x + (size_t)(b * C_ + n) * HIM * WIM;
        float m = -INFINITY;
        int i0 = 2 * hh - 1, j0 = 2 * ww - 1;
        #pragma unroll
        for (int di = 0; di < 3; di++) {
            int i = i0 + di; if (i < 0 || i >= HIM) continue;
            #pragma unroll
            for (int dj = 0; dj < 3; dj++) {
                int j = j0 + dj; if (j < 0 || j >= WIM) continue;
                m = fmaxf(m, xp[i * WIM + j]);
            }
        }
        val = m;
    } else {
        int g = (n - 128) >> 7;
        int c = (n - 128) & 127;
        const float* xp = x + (size_t)(b * C_ + c) * HIM * WIM;
        float a  = xp[(2 * hh) * WIM + 2 * ww];
        float bb = xp[(2 * hh) * WIM + 2 * ww + 1];
        float cc = xp[(2 * hh + 1) * WIM + 2 * ww];
        float dd = xp[(2 * hh + 1) * WIM + 2 * ww + 1];
        if      (g == 0) val = (a + bb + cc + dd) * 0.5f;
        else if (g == 1) val = (a - bb + cc - dd) * 0.5f;
        else if (g == 2) val = (a + bb - cc - dd) * 0.5f;
        else             val = (a - bb - cc + dd) * 0.5f;
    }
    g_tokens[idx] = val;
}

// ---------------- stage 2: qk/v GEMM (tokens @ [w_qk | w_v]) ---------------
// M=10240, K=256, N=512. Tile 64x64x16, 256 threads, 4x4 microtile.
__global__ __launch_bounds__(256) void k_gemm_qkv(const float* __restrict__ wqk,
                                                  const float* __restrict__ wv) {
    __shared__ float As[64][16];
    __shared__ float Bs[16][64];
    int bm = blockIdx.y * 64;
    int bn = blockIdx.x * 64;          // 0..448
    const float* Bmat = (bn < 256) ? wqk : wv;
    int bncol = (bn < 256) ? bn : bn - 256;
    int tid = threadIdx.x;
    int tx = tid & 15, ty = tid >> 4;
    float acc[4][4] = {};

    for (int k0 = 0; k0 < S_; k0 += 16) {
        {   // A tile: 64x16, float4 per thread
            int i = tid * 4;
            int r = i >> 4, c = i & 15;
            float4 av = *(const float4*)&g_tokens[(size_t)(bm + r) * S_ + k0 + c];
            As[r][c] = av.x; As[r][c + 1] = av.y; As[r][c + 2] = av.z; As[r][c + 3] = av.w;
        }
        {   // B tile: 16x64
            int i = tid * 4;
            int r = i >> 6, c = i & 63;
            float4 bv = *(const float4*)&Bmat[(size_t)(k0 + r) * EMBD + bncol + c];
            *(float4*)&Bs[r][c] = bv;
        }
        __syncthreads();
        #pragma unroll
        for (int kk = 0; kk < 16; kk++) {
            float a[4];
            #pragma unroll
            for (int r = 0; r < 4; r++) a[r] = As[ty * 4 + r][kk];
            float4 b4 = *(const float4*)&Bs[kk][tx * 4];
            float bb[4] = {b4.x, b4.y, b4.z, b4.w};
            #pragma unroll
            for (int r = 0; r < 4; r++)
                #pragma unroll
                for (int c = 0; c < 4; c++)
                    acc[r][c] += a[r] * bb[c];
        }
        __syncthreads();
    }
    // scatter epilogue into head-major qk/v: (bh=b*8+head, t=n, dh)
    #pragma unroll
    for (int r = 0; r < 4; r++) {
        int m = bm + ty * 4 + r;
        int b = m / T_, n = m % T_;
        #pragma unroll
        for (int c = 0; c < 4; c++) {
            int e = bn + tx * 4 + c;
            float vv = acc[r][c];
            if (e < 256) {
                int head = e >> 5, dh = e & 31;
                g_qk[((size_t)(b * NHEAD + head) * T_ + n) * DH + dh] = vv;
            } else {
                int e2 = e - 256;
                int head = e2 >> 5, dh = e2 & 31;
                g_v[((size_t)(b * NHEAD + head) * T_ + n) * DH + dh] = vv;
            }
        }
    }
}

// ---------------- stage 3: LSH buckets ------------------------------------
__global__ __launch_bounds__(256) void k_buckets(const float* __restrict__ rot) {
    __shared__ float srot[DH * NH * 5];      // 1280
    for (int i = threadIdx.x; i < DH * NH * 5; i += 256) srot[i] = rot[i];
    __syncthreads();
    int gid = blockIdx.x * 256 + threadIdx.x;
    if (gid >= BH * T_) return;
    int bh = gid / T_, t = gid % T_;
    float q[DH];
    const float* qp = &g_qk[((size_t)bh * T_ + t) * DH];
    #pragma unroll
    for (int f = 0; f < DH; f++) q[f] = qp[f];
    #pragma unroll
    for (int h = 0; h < NH; h++) {
        float s[5] = {0, 0, 0, 0, 0};
        for (int f = 0; f < DH; f++) {
            float qf = q[f];
            #pragma unroll
            for (int i = 0; i < 5; i++) s[i] += qf * srot[f * (NH * 5) + h * 5 + i];
        }
        // argmax over [s0..s4, -s0..-s4] with first-max tiebreak (matches jnp.argmax)
        float best = s[0]; int bi = 0;
        #pragma unroll
        for (int i = 1; i < 5; i++) if (s[i] > best) { best = s[i]; bi = i; }
        #pragma unroll
        for (int i = 0; i < 5; i++) if (-s[i] > best) { best = -s[i]; bi = 5 + i; }
        g_bkt[(size_t)(bh * NH + h) * T_ + t] = bi;
    }
}

// ---------------- stage 4: stable counting sort per (bh, hash) -------------
// Rank via per-warp bucket-membership ballots: rank(t) = sum of popcounts of
// earlier warps' masks for my bucket + masked popcount within my warp.
// Stability: (warp, lane) order == token order.
__global__ __launch_bounds__(T_) void k_sort() {
    int bhh = blockIdx.x;                 // bh*8 + h
    __shared__ unsigned smask[T_ / 32][NB];   // 20 x 10
    __shared__ int off[NB];
    int t = threadIdx.x;
    int w = t >> 5, lane = t & 31;
    int b = g_bkt[(size_t)bhh * T_ + t];
    #pragma unroll
    for (int bb = 0; bb < NB; bb++) {
        unsigned m = __ballot_sync(0xffffffff, b == bb);
        if (lane == 0) smask[w][bb] = m;
    }
    __syncthreads();
    if (t == 0) {
        int acc = 0;
        #pragma unroll
        for (int i = 0; i < NB; i++) {
            off[i] = acc;
            int c = 0;
            #pragma unroll
            for (int ww = 0; ww < T_ / 32; ww++) c += __popc(smask[ww][i]);
            acc += c;
        }
    }
    __syncthreads();
    int rank = 0;
    for (int ww = 0; ww < w; ww++) rank += __popc(smask[ww][b]);
    rank += __popc(smask[w][b] & ((1u << lane) - 1u));
    g_st[(size_t)bhh * T_ + off[b] + rank] = t;
}

// ---------------- stage 5: chunked attention -------------------------------
// Block handles 32 queries (half of a 64-chunk) against 128 keys (chunk + prev).
// grid = (160, 128): x = chunk*2 + half, y = bh. 256 threads.
__global__ __launch_bounds__(256) void k_attn() {
    __shared__ float sQ[32][32];          // queries
    __shared__ float sKV[128][36];        // keys, then reused for values
    __shared__ float sS[32][132];         // scores -> probs
    __shared__ int   sQT[32], sKT[128];
    __shared__ float sLse[32];

    int bh = blockIdx.y;
    int n  = blockIdx.x >> 1;             // chunk 0..79
    int hf = blockIdx.x & 1;
    int h  = n / NB;
    int np = (n + NC - 1) % NC;           // look-one-back chunk (circular in bh)
    int hp = np / NB;
    int tid = threadIdx.x;
    const int* stb = &g_st[(size_t)bh * NH * T_];

    if (tid < 128) {
        int kt = (tid < 64) ? stb[h * T_ + (n % NB) * 64 + tid]
                            : stb[hp * T_ + (np % NB) * 64 + (tid - 64)];
        sKT[tid] = kt;
        if (tid < 32) sQT[tid] = stb[h * T_ + (n % NB) * 64 + hf * 32 + tid];
    }
    __syncthreads();

    {   // load q: 32x32, float4 per thread
        int i = tid >> 3, d = (tid & 7) * 4;
        float4 qv = *(const float4*)&g_qk[((size_t)bh * T_ + sQT[i]) * DH + d];
        sQ[i][d] = qv.x; sQ[i][d + 1] = qv.y; sQ[i][d + 2] = qv.z; sQ[i][d + 3] = qv.w;
    }
    {   // load k raw: 128x32, 16 floats per thread
        int j = tid >> 1, d0 = (tid & 1) * 16;
        const float* kp = &g_qk[((size_t)bh * T_ + sKT[j]) * DH + d0];
        #pragma unroll
        for (int u = 0; u < 16; u += 4) {
            float4 kv = *(const float4*)&kp[u];
            sKV[j][d0 + u] = kv.x; sKV[j][d0 + u + 1] = kv.y;
            sKV[j][d0 + u + 2] = kv.z; sKV[j][d0 + u + 3] = kv.w;
        }
    }
    __syncthreads();
    if (tid < 128) {                       // normalize keys: k / max(||k||, 1e-6)
        float ss = 0;
        #pragma unroll
        for (int d = 0; d < DH; d++) { float v = sKV[tid][d]; ss += v * v; }
        float inv = 1.0f / fmaxf(sqrtf(ss), 1e-6f);
        #pragma unroll
        for (int d = 0; d < DH; d++) sKV[tid][d] *= inv;
    }
    __syncthreads();

    {   // scores: 2 rows x 8 cols per thread
        int it = tid >> 4;                // 0..15
        int jt = tid & 15;                // 0..15
        float acc0[8] = {}, acc1[8] = {};
        #pragma unroll 8
        for (int d = 0; d < DH; d++) {
            float q0 = sQ[2 * it][d], q1 = sQ[2 * it + 1][d];
            #pragma unroll
            for (int c = 0; c < 8; c++) {
                float kv = sKV[8 * jt + c][d];
                acc0[c] += q0 * kv;
                acc1[c] += q1 * kv;
            }
        }
        const float scale = 0.17677669529663687f;   // 32^-0.5
        int i0 = 2 * it;
        int qt0 = sQT[i0], qt1 = sQT[i0 + 1];
        #pragma unroll
        for (int c = 0; c < 8; c++) {
            int j = 8 * jt + c;
            int kt = sKT[j];
            sS[i0][j]     = (qt0 == kt) ? -50000.0f : acc0[c] * scale;
            sS[i0 + 1][j] = (qt1 == kt) ? -50000.0f : acc1[c] * scale;
        }
    }
    __syncthreads();

    {   // load v into sKV (k is dead) — safe: all score reads synced above
        int j = tid >> 1, d0 = (tid & 1) * 16;
        const float* vp = &g_v[((size_t)bh * T_ + sKT[j]) * DH + d0];
        #pragma unroll
        for (int u = 0; u < 16; u += 4) {
            float4 vv = *(const float4*)&vp[u];
            sKV[j][d0 + u] = vv.x; sKV[j][d0 + u + 1] = vv.y;
            sKV[j][d0 + u + 2] = vv.z; sKV[j][d0 + u + 3] = vv.w;
        }
    }
    {   // softmax: 8 threads per row, 16 entries each (touches only sS/sLse)
        int row = tid >> 3, part = tid & 7;
        float m = -INFINITY;
        #pragma unroll
        for (int u = 0; u < 16; u++) m = fmaxf(m, sS[row][part * 16 + u]);
        m = fmaxf(m, __shfl_xor_sync(0xffffffff, m, 1, 8));
        m = fmaxf(m, __shfl_xor_sync(0xffffffff, m, 2, 8));
        m = fmaxf(m, __shfl_xor_sync(0xffffffff, m, 4, 8));
        float sum = 0;
        #pragma unroll
        for (int u = 0; u < 16; u++) sum += expf(sS[row][part * 16 + u] - m);
        sum += __shfl_xor_sync(0xffffffff, sum, 1, 8);
        sum += __shfl_xor_sync(0xffffffff, sum, 2, 8);
        sum += __shfl_xor_sync(0xffffffff, sum, 4, 8);
        float inv = 1.0f / sum;
        #pragma unroll
        for (int u = 0; u < 16; u++)
            sS[row][part * 16 + u] = expf(sS[row][part * 16 + u] - m) * inv;
        if (part == 0) sLse[row] = m + logf(sum);
    }
    __syncthreads();

    {   // PV: 1 row x 4 dims per thread; scatter by original token id (kills `undo`)
        int i = tid >> 3, dc = (tid & 7) * 4;
        float a0 = 0, a1 = 0, a2 = 0, a3 = 0;
        #pragma unroll 4
        for (int j = 0; j < 128; j++) {
            float p = sS[i][j];
            float4 vv = *(const float4*)&sKV[j][dc];
            a0 += p * vv.x; a1 += p * vv.y; a2 += p * vv.z; a3 += p * vv.w;
        }
        int qt = sQT[i];
        size_t base = ((size_t)(bh * NH + h) * T_ + qt) * DH + dc;
        *(float4*)&g_oh[base] = make_float4(a0, a1, a2, a3);
        if ((tid & 7) == 0) g_lse[(size_t)(bh * NH + h) * T_ + qt] = sLse[i];
    }
}

// ---------------- stage 6: combine over hashes -----------------------------
__global__ __launch_bounds__(256) void k_combine() {
    int w = blockIdx.x * 8 + (threadIdx.x >> 5);
    int lane = threadIdx.x & 31;
    int bh = w / T_, t = w % T_;
    float l[NH];
    #pragma unroll
    for (int h = 0; h < NH; h++) l[h] = g_lse[(size_t)(bh * NH + h) * T_ + t];
    float m = l[0];
    #pragma unroll
    for (int h = 1; h < NH; h++) m = fmaxf(m, l[h]);
    float sum = 0;
    #pragma unroll
    for (int h = 0; h < NH; h++) sum += expf(l[h] - m);
    float inv = 1.0f / sum;
    float o = 0;
    #pragma unroll
    for (int h = 0; h < NH; h++)
        o += expf(l[h] - m) * inv * g_oh[((size_t)(bh * NH + h) * T_ + t) * DH + lane];
    g_of[((size_t)bh * T_ + t) * DH + lane] = o;
}

// ---------------- stage 7: output GEMM + bias ------------------------------
// out(10240x256) = gather(g_of) @ w_out + b_out; written as (B, N, 16, 16)
__global__ __launch_bounds__(256) void k_gemm_out(const float* __restrict__ wout,
                                                  const float* __restrict__ bias,
                                                  float* __restrict__ out) {
    __shared__ float As[64][16];
    __shared__ float Bs[16][64];
    int bm = blockIdx.y * 64;
    int bn = blockIdx.x * 64;
    int tid = threadIdx.x;
    int tx = tid & 15, ty = tid >> 4;
    float acc[4][4] = {};

    for (int k0 = 0; k0 < EMBD; k0 += 16) {
        {   // gather A from head-major g_of
            int i = tid * 4;
            int r = i >> 4, c = i & 15;
            int m = bm + r;
            int b = m / T_, n = m % T_;
            int k = k0 + c;
            int head = k >> 5, dh = k & 31;      // head constant across 4 consecutive k
            float4 av = *(const float4*)&g_of[((size_t)(b * NHEAD + head) * T_ + n) * DH + dh];
            As[r][c] = av.x; As[r][c + 1] = av.y; As[r][c + 2] = av.z; As[r][c + 3] = av.w;
        }
        {
            int i = tid * 4;
            int r = i >> 6, c = i & 63;
            float4 bv = *(const float4*)&wout[(size_t)(k0 + r) * EMBD + bn + c];
            *(float4*)&Bs[r][c] = bv;
        }
        __syncthreads();
        #pragma unroll
        for (int kk = 0; kk < 16; kk++) {
            float a[4];
            #pragma unroll
            for (int r = 0; r < 4; r++) a[r] = As[ty * 4 + r][kk];
            float4 b4 = *(const float4*)&Bs[kk][tx * 4];
            float bb[4] = {b4.x, b4.y, b4.z, b4.w};
            #pragma unroll
            for (int r = 0; r < 4; r++)
                #pragma unroll
                for (int c = 0; c < 4; c++)
                    acc[r][c] += a[r] * bb[c];
        }
        __syncthreads();
    }
    #pragma unroll
    for (int r = 0; r < 4; r++) {
        int m = bm + ty * 4 + r;
        #pragma unroll
        for (int c = 0; c < 4; c++) {
            int e = bn + tx * 4 + c;
            out[(size_t)m * EMBD + e] = acc[r][c] + bias[e];
        }
    }
}

// ---------------- launch ----------------------------------------------------
extern "C" void kernel_launch(void* const* d_in, const int* in_sizes, int n_in,
                              void* d_out, int out_size) {
    const float* x    = (const float*)d_in[0];
    const float* wqk  = (const float*)d_in[1];
    const float* wv   = (const float*)d_in[2];
    const float* wout = (const float*)d_in[3];
    const float* bout = (const float*)d_in[4];
    const float* rot  = (const float*)d_in[5];
    float* out = (float*)d_out;

    k_tokens  <<<(B_ * NTOK * S_ + 255) / 256, 256>>>(x);
    k_gemm_qkv<<<dim3(8, 160), 256>>>(wqk, wv);
    k_buckets <<<(BH * T_ + 255) / 256, 256>>>(rot);
    k_sort    <<<BH * NH, T_>>>();
    k_attn    <<<dim3(160, 128), 256>>>();
    k_combine <<<BH * T_ / 8, 256>>>();
    k_gemm_out<<<dim3(4, 160), 256>>>(wout, bout, out);
}

// round 5
// speedup vs baseline: 2.6953x; 2.6953x over previous
#include <cuda_runtime.h>
#include <math.h>

#define B_    16
#define C_    128
#define HIM   32
#define WIM   32
#define NTOK  640
#define S_    256     // spatial 16x16 == GEMM K == EMB
#define EMBD  256
#define NHEAD 8
#define DH    32
#define BH    128     // B_*NHEAD
#define T_    640
#define NH    8       // n_hashes
#define NB    10      // n_buckets per hash
#define NC    80      // chunks per bh (NH*NB)

// ---------------- scratch (device globals; no allocation allowed) ----------
__device__ float g_tokens[B_ * NTOK * S_];        // (b, n, s)
__device__ float g_qk[BH * T_ * DH];              // (bh, t, d)
__device__ float g_v [BH * T_ * DH];
__device__ int   g_bkt[BH * NH * T_];             // bucket in [0,10)
__device__ int   g_st [BH * NH * T_];             // sorted pos -> token id
__device__ float g_oh [BH * NH * T_ * DH];        // per-hash output (scattered by token)
__device__ float g_lse[BH * NH * T_];
__device__ float g_of [BH * T_ * DH];             // combined over hashes

// ---------------- stage 1: maxpool + Haar -> tokens ------------------------
__global__ __launch_bounds__(256) void k_tokens(const float* __restrict__ x) {
    int idx = blockIdx.x * 256 + threadIdx.x;
    if (idx >= B_ * NTOK * S_) return;
    int s = idx & 255;
    int n = (idx >> 8) % NTOK;
    int b = idx / (NTOK * S_);
    int hh = s >> 4, ww = s & 15;
    float val;
    if (n < 128) {
        const float* xp = x + (size_t)(b * C_ + n) * HIM * WIM;
        float m = -INFINITY;
        int i0 = 2 * hh - 1, j0 = 2 * ww - 1;
        #pragma unroll
        for (int di = 0; di < 3; di++) {
            int i = i0 + di; if (i < 0 || i >= HIM) continue;
            #pragma unroll
            for (int dj = 0; dj < 3; dj++) {
                int j = j0 + dj; if (j < 0 || j >= WIM) continue;
                m = fmaxf(m, xp[i * WIM + j]);
            }
        }
        val = m;
    } else {
        int g = (n - 128) >> 7;
        int c = (n - 128) & 127;
        const float* xp = x + (size_t)(b * C_ + c) * HIM * WIM;
        float a  = xp[(2 * hh) * WIM + 2 * ww];
        float bb = xp[(2 * hh) * WIM + 2 * ww + 1];
        float cc = xp[(2 * hh + 1) * WIM + 2 * ww];
        float dd = xp[(2 * hh + 1) * WIM + 2 * ww + 1];
        if      (g == 0) val = (a + bb + cc + dd) * 0.5f;
        else if (g == 1) val = (a - bb + cc - dd) * 0.5f;
        else if (g == 2) val = (a + bb - cc - dd) * 0.5f;
        else             val = (a - bb - cc + dd) * 0.5f;
    }
    g_tokens[idx] = val;
}

// ---------------- stage 2: qk/v GEMM (tokens @ [w_qk | w_v]) ---------------
__global__ __launch_bounds__(256) void k_gemm_qkv(const float* __restrict__ wqk,
                                                  const float* __restrict__ wv) {
    __shared__ float As[64][16];
    __shared__ float Bs[16][64];
    int bm = blockIdx.y * 64;
    int bn = blockIdx.x * 64;          // 0..448
    const float* Bmat = (bn < 256) ? wqk : wv;
    int bncol = (bn < 256) ? bn : bn - 256;
    int tid = threadIdx.x;
    int tx = tid & 15, ty = tid >> 4;
    float acc[4][4] = {};

    for (int k0 = 0; k0 < S_; k0 += 16) {
        {   // A tile: 64x16, float4 per thread
            int i = tid * 4;
            int r = i >> 4, c = i & 15;
            float4 av = *(const float4*)&g_tokens[(size_t)(bm + r) * S_ + k0 + c];
            As[r][c] = av.x; As[r][c + 1] = av.y; As[r][c + 2] = av.z; As[r][c + 3] = av.w;
        }
        {   // B tile: 16x64
            int i = tid * 4;
            int r = i >> 6, c = i & 63;
            float4 bv = *(const float4*)&Bmat[(size_t)(k0 + r) * EMBD + bncol + c];
            *(float4*)&Bs[r][c] = bv;
        }
        __syncthreads();
        #pragma unroll
        for (int kk = 0; kk < 16; kk++) {
            float a[4];
            #pragma unroll
            for (int r = 0; r < 4; r++) a[r] = As[ty * 4 + r][kk];
            float4 b4 = *(const float4*)&Bs[kk][tx * 4];
            float bb[4] = {b4.x, b4.y, b4.z, b4.w};
            #pragma unroll
            for (int r = 0; r < 4; r++)
                #pragma unroll
                for (int c = 0; c < 4; c++)
                    acc[r][c] += a[r] * bb[c];
        }
        __syncthreads();
    }
    #pragma unroll
    for (int r = 0; r < 4; r++) {
        int m = bm + ty * 4 + r;
        int b = m / T_, n = m % T_;
        #pragma unroll
        for (int c = 0; c < 4; c++) {
            int e = bn + tx * 4 + c;
            float vv = acc[r][c];
            if (e < 256) {
                int head = e >> 5, dh = e & 31;
                g_qk[((size_t)(b * NHEAD + head) * T_ + n) * DH + dh] = vv;
            } else {
                int e2 = e - 256;
                int head = e2 >> 5, dh = e2 & 31;
                g_v[((size_t)(b * NHEAD + head) * T_ + n) * DH + dh] = vv;
            }
        }
    }
}

// ---------------- stage 3: LSH buckets ------------------------------------
__global__ __launch_bounds__(256) void k_buckets(const float* __restrict__ rot) {
    __shared__ float srot[DH * NH * 5];      // 1280
    for (int i = threadIdx.x; i < DH * NH * 5; i += 256) srot[i] = rot[i];
    __syncthreads();
    int gid = blockIdx.x * 256 + threadIdx.x;
    if (gid >= BH * T_) return;
    int bh = gid / T_, t = gid % T_;
    float q[DH];
    const float* qp = &g_qk[((size_t)bh * T_ + t) * DH];
    #pragma unroll
    for (int f = 0; f < DH; f++) q[f] = qp[f];
    #pragma unroll
    for (int h = 0; h < NH; h++) {
        float s[5] = {0, 0, 0, 0, 0};
        for (int f = 0; f < DH; f++) {
            float qf = q[f];
            #pragma unroll
            for (int i = 0; i < 5; i++) s[i] += qf * srot[f * (NH * 5) + h * 5 + i];
        }
        float best = s[0]; int bi = 0;
        #pragma unroll
        for (int i = 1; i < 5; i++) if (s[i] > best) { best = s[i]; bi = i; }
        #pragma unroll
        for (int i = 0; i < 5; i++) if (-s[i] > best) { best = -s[i]; bi = 5 + i; }
        g_bkt[(size_t)(bh * NH + h) * T_ + t] = bi;
    }
}

// ---------------- stage 4: stable counting sort per (bh, hash) -------------
__global__ __launch_bounds__(T_) void k_sort() {
    int bhh = blockIdx.x;                 // bh*8 + h
    __shared__ unsigned smask[T_ / 32][NB];   // 20 x 10
    __shared__ int off[NB];
    int t = threadIdx.x;
    int w = t >> 5, lane = t & 31;
    int b = g_bkt[(size_t)bhh * T_ + t];
    #pragma unroll
    for (int bb = 0; bb < NB; bb++) {
        unsigned m = __ballot_sync(0xffffffff, b == bb);
        if (lane == 0) smask[w][bb] = m;
    }
    __syncthreads();
    if (t == 0) {
        int acc = 0;
        #pragma unroll
        for (int i = 0; i < NB; i++) {
            off[i] = acc;
            int c = 0;
            #pragma unroll
            for (int ww = 0; ww < T_ / 32; ww++) c += __popc(smask[ww][i]);
            acc += c;
        }
    }
    __syncthreads();
    int rank = 0;
    for (int ww = 0; ww < w; ww++) rank += __popc(smask[ww][b]);
    rank += __popc(smask[w][b] & ((1u << lane) - 1u));
    g_st[(size_t)bhh * T_ + off[b] + rank] = t;
}

// ---------------- stage 5: chunked attention (conflict-free, 64q) ----------
// Block: one 64-query chunk vs 128 keys (chunk + look-back). grid (80, 128).
// Dynamic smem layout (floats):
//   sS  [64][132]   scores->probs         @ 0      (8448)
//   sKV             K^T [32][136] then V [128][36]  @ 8448  (4608)
//   sQ  [64][36]                          @ 13056  (2304)
//   sTid[128] (int)                       @ 15360  (128)
//   sLse[64]                              @ 15488  (64)
// total 15552 floats = 62208 bytes
#define ATTN_SMEM 62208
__global__ __launch_bounds__(256) void k_attn() {
    extern __shared__ float smem[];
    float* sS   = smem;                    // stride 132
    float* sKV  = smem + 8448;             // K^T stride 136 (d-major), then V stride 36
    float* sQ   = smem + 13056;            // stride 36
    int*   sTid = (int*)(smem + 15360);
    float* sLse = smem + 15488;

    int bh = blockIdx.y;
    int n  = blockIdx.x;                  // chunk 0..79
    int h  = n / NB;
    int np = (n + NC - 1) % NC;           // look-one-back chunk (circular in bh)
    int hp = np / NB;
    int tid = threadIdx.x;
    const int* stb = &g_st[(size_t)bh * NH * T_];

    if (tid < 128) {
        int kt = (tid < 64) ? stb[h * T_ + (n % NB) * 64 + tid]
                            : stb[hp * T_ + (np % NB) * 64 + (tid - 64)];
        sTid[tid] = kt;
    }
    __syncthreads();

    {   // Q: 64x32, 8 floats per thread (queries == keys 0..63)
        int i = tid >> 2, d0 = (tid & 3) * 8;
        const float* qp = &g_qk[((size_t)bh * T_ + sTid[i]) * DH + d0];
        float4 a = *(const float4*)qp;
        float4 b = *(const float4*)(qp + 4);
        *(float4*)&sQ[i * 36 + d0]     = a;
        *(float4*)&sQ[i * 36 + d0 + 4] = b;
    }
    {   // K: transpose into sKV[d][j], normalizing on the fly.
        int j = tid >> 1, d0 = (tid & 1) * 16;
        const float* kp = &g_qk[((size_t)bh * T_ + sTid[j]) * DH + d0];
        float kv[16];
        #pragma unroll
        for (int u = 0; u < 16; u += 4) {
            float4 t4 = *(const float4*)&kp[u];
            kv[u] = t4.x; kv[u + 1] = t4.y; kv[u + 2] = t4.z; kv[u + 3] = t4.w;
        }
        float ss = 0;
        #pragma unroll
        for (int u = 0; u < 16; u++) ss += kv[u] * kv[u];
        ss += __shfl_xor_sync(0xffffffff, ss, 1);   // pair shares key j
        float inv = 1.0f / fmaxf(sqrtf(ss), 1e-6f);
        #pragma unroll
        for (int u = 0; u < 16; u++) sKV[(d0 + u) * 136 + j] = kv[u] * inv;
    }
    __syncthreads();

    {   // scores: 4 rows x 8 cols per thread; K loads are LDS.128 on K^T
        int ty = tid >> 4, tx = tid & 15;
        float acc[4][8] = {};
        #pragma unroll 4
        for (int d = 0; d < DH; d++) {
            float4 k0 = *(const float4*)&sKV[d * 136 + tx * 8];
            float4 k1 = *(const float4*)&sKV[d * 136 + tx * 8 + 4];
            float kk[8] = {k0.x, k0.y, k0.z, k0.w, k1.x, k1.y, k1.z, k1.w};
            #pragma unroll
            for (int r = 0; r < 4; r++) {
                float q = sQ[(ty * 4 + r) * 36 + d];
                #pragma unroll
                for (int c = 0; c < 8; c++) acc[r][c] += q * kk[c];
            }
        }
        const float scale = 0.17677669529663687f;   // 32^-0.5
        #pragma unroll
        for (int r = 0; r < 4; r++) {
            int row = ty * 4 + r;
            int qt = sTid[row];
            float o[8];
            #pragma unroll
            for (int c = 0; c < 8; c++) {
                int kt = sTid[tx * 8 + c];
                o[c] = (qt == kt) ? -50000.0f : acc[r][c] * scale;
            }
            *(float4*)&sS[row * 132 + tx * 8]     = make_float4(o[0], o[1], o[2], o[3]);
            *(float4*)&sS[row * 132 + tx * 8 + 4] = make_float4(o[4], o[5], o[6], o[7]);
        }
    }
    __syncthreads();

    {   // V into sKV (row-major, K^T dead) — touches only sKV
        int j = tid >> 1, d0 = (tid & 1) * 16;
        const float* vp = &g_v[((size_t)bh * T_ + sTid[j]) * DH + d0];
        #pragma unroll
        for (int u = 0; u < 16; u += 4)
            *(float4*)&sKV[j * 36 + d0 + u] = *(const float4*)&vp[u];
    }
    {   // softmax: 4 threads per row, 32 entries each — touches only sS/sLse
        int row = tid >> 2, part = tid & 3;
        float v[32];
        #pragma unroll
        for (int u = 0; u < 8; u++) {
            float4 t4 = *(const float4*)&sS[row * 132 + part * 32 + u * 4];
            v[4*u] = t4.x; v[4*u+1] = t4.y; v[4*u+2] = t4.z; v[4*u+3] = t4.w;
        }
        float m = v[0];
        #pragma unroll
        for (int u = 1; u < 32; u++) m = fmaxf(m, v[u]);
        m = fmaxf(m, __shfl_xor_sync(0xffffffff, m, 1));
        m = fmaxf(m, __shfl_xor_sync(0xffffffff, m, 2));
        float sum = 0;
        #pragma unroll
        for (int u = 0; u < 32; u++) { v[u] = __expf(v[u] - m); sum += v[u]; }
        sum += __shfl_xor_sync(0xffffffff, sum, 1);
        sum += __shfl_xor_sync(0xffffffff, sum, 2);
        float inv = 1.0f / sum;
        #pragma unroll
        for (int u = 0; u < 8; u++)
            *(float4*)&sS[row * 132 + part * 32 + u * 4] =
                make_float4(v[4*u] * inv, v[4*u+1] * inv, v[4*u+2] * inv, v[4*u+3] * inv);
        if (part == 0) sLse[row] = m + __logf(sum);
    }
    __syncthreads();

    {   // PV: 2 rows x 4 dims per thread, j blocked by 4 (all float4)
        int qi = tid >> 3;                // 0..31 -> rows 2qi, 2qi+1
        int dc = (tid & 7) * 4;
        float4 a0 = make_float4(0, 0, 0, 0), a1 = make_float4(0, 0, 0, 0);
        #pragma unroll 4
        for (int j = 0; j < 128; j += 4) {
            float4 p0 = *(const float4*)&sS[(2 * qi) * 132 + j];
            float4 p1 = *(const float4*)&sS[(2 * qi + 1) * 132 + j];
            float p0a[4] = {p0.x, p0.y, p0.z, p0.w};
            float p1a[4] = {p1.x, p1.y, p1.z, p1.w};
            #pragma unroll
            for (int u = 0; u < 4; u++) {
                float4 vv = *(const float4*)&sKV[(j + u) * 36 + dc];
                a0.x += p0a[u] * vv.x; a0.y += p0a[u] * vv.y;
                a0.z += p0a[u] * vv.z; a0.w += p0a[u] * vv.w;
                a1.x += p1a[u] * vv.x; a1.y += p1a[u] * vv.y;
                a1.z += p1a[u] * vv.z; a1.w += p1a[u] * vv.w;
            }
        }
        int qt0 = sTid[2 * qi], qt1 = sTid[2 * qi + 1];
        size_t hb = (size_t)(bh * NH + h) * T_;
        *(float4*)&g_oh[(hb + qt0) * DH + dc] = a0;
        *(float4*)&g_oh[(hb + qt1) * DH + dc] = a1;
        if ((tid & 7) == 0) {
            g_lse[hb + qt0] = sLse[2 * qi];
            g_lse[hb + qt1] = sLse[2 * qi + 1];
        }
    }
}

// ---------------- stage 6: combine over hashes -----------------------------
__global__ __launch_bounds__(256) void k_combine() {
    int w = blockIdx.x * 8 + (threadIdx.x >> 5);
    int lane = threadIdx.x & 31;
    int bh = w / T_, t = w % T_;
    float l[NH];
    #pragma unroll
    for (int h = 0; h < NH; h++) l[h] = g_lse[(size_t)(bh * NH + h) * T_ + t];
    float m = l[0];
    #pragma unroll
    for (int h = 1; h < NH; h++) m = fmaxf(m, l[h]);
    float sum = 0;
    #pragma unroll
    for (int h = 0; h < NH; h++) { l[h] = __expf(l[h] - m); sum += l[h]; }
    float inv = 1.0f / sum;
    float o = 0;
    #pragma unroll
    for (int h = 0; h < NH; h++)
        o += l[h] * inv * g_oh[((size_t)(bh * NH + h) * T_ + t) * DH + lane];
    g_of[((size_t)bh * T_ + t) * DH + lane] = o;
}

// ---------------- stage 7: output GEMM + bias ------------------------------
__global__ __launch_bounds__(256) void k_gemm_out(const float* __restrict__ wout,
                                                  const float* __restrict__ bias,
                                                  float* __restrict__ out) {
    __shared__ float As[64][16];
    __shared__ float Bs[16][64];
    int bm = blockIdx.y * 64;
    int bn = blockIdx.x * 64;
    int tid = threadIdx.x;
    int tx = tid & 15, ty = tid >> 4;
    float acc[4][4] = {};

    for (int k0 = 0; k0 < EMBD; k0 += 16) {
        {   // gather A from head-major g_of
            int i = tid * 4;
            int r = i >> 4, c = i & 15;
            int m = bm + r;
            int b = m / T_, n = m % T_;
            int k = k0 + c;
            int head = k >> 5, dh = k & 31;
            float4 av = *(const float4*)&g_of[((size_t)(b * NHEAD + head) * T_ + n) * DH + dh];
            As[r][c] = av.x; As[r][c + 1] = av.y; As[r][c + 2] = av.z; As[r][c + 3] = av.w;
        }
        {
            int i = tid * 4;
            int r = i >> 6, c = i & 63;
            float4 bv = *(const float4*)&wout[(size_t)(k0 + r) * EMBD + bn + c];
            *(float4*)&Bs[r][c] = bv;
        }
        __syncthreads();
        #pragma unroll
        for (int kk = 0; kk < 16; kk++) {
            float a[4];
            #pragma unroll
            for (int r = 0; r < 4; r++) a[r] = As[ty * 4 + r][kk];
            float4 b4 = *(const float4*)&Bs[kk][tx * 4];
            float bb[4] = {b4.x, b4.y, b4.z, b4.w};
            #pragma unroll
            for (int r = 0; r < 4; r++)
                #pragma unroll
                for (int c = 0; c < 4; c++)
                    acc[r][c] += a[r] * bb[c];
        }
        __syncthreads();
    }
    #pragma unroll
    for (int r = 0; r < 4; r++) {
        int m = bm + ty * 4 + r;
        #pragma unroll
        for (int c = 0; c < 4; c++) {
            int e = bn + tx * 4 + c;
            out[(size_t)m * EMBD + e] = acc[r][c] + bias[e];
        }
    }
}

// ---------------- launch ----------------------------------------------------
extern "C" void kernel_launch(void* const* d_in, const int* in_sizes, int n_in,
                              void* d_out, int out_size) {
    const float* x    = (const float*)d_in[0];
    const float* wqk  = (const float*)d_in[1];
    const float* wv   = (const float*)d_in[2];
    const float* wout = (const float*)d_in[3];
    const float* bout = (const float*)d_in[4];
    const float* rot  = (const float*)d_in[5];
    float* out = (float*)d_out;

    cudaFuncSetAttribute(k_attn, cudaFuncAttributeMaxDynamicSharedMemorySize, ATTN_SMEM);

    k_tokens  <<<(B_ * NTOK * S_ + 255) / 256, 256>>>(x);
    k_gemm_qkv<<<dim3(8, 160), 256>>>(wqk, wv);
    k_buckets <<<(BH * T_ + 255) / 256, 256>>>(rot);
    k_sort    <<<BH * NH, T_>>>();
    k_attn    <<<dim3(80, 128), 256, ATTN_SMEM>>>();
    k_combine <<<BH * T_ / 8, 256>>>();
    k_gemm_out<<<dim3(4, 160), 256>>>(wout, bout, out);
}